// round 1
// baseline (speedup 1.0000x reference)
#include <cuda_runtime.h>

// Problem constants
#define BB   8
#define TT   1024
#define CC   512
#define HH   8
#define HD   64
#define NR   137      // 2*MAXR + 1
#define MAXR 68
#define BH   64       // BB*HH
#define MM   8192     // BB*TT

// Scratch (device globals; no runtime allocation allowed)
static __device__ float g_q[BH * TT * HD];          // (bh, t, d)
static __device__ float g_k[BH * TT * HD];
static __device__ float g_v[BH * TT * HD];
static __device__ float g_proj[BH * TT * NR];       // q . rel_k^T
static __device__ float g_S[67108864];              // (bh, t, k)  attn logits -> probs (268MB)
static __device__ float g_sb[BH * TT * NR];         // bucket sums s[q, r]
static __device__ float g_y[MM * CC];               // pre-output-proj activations

// ---------------------------------------------------------------------------
// 128x128 fp32 GEMM tile helper: C[128,128] += A[row0:+128, :CC] * W[:, col0:+128]
// block = 256 threads, 8x8 microtile per thread, BK = 8
// ---------------------------------------------------------------------------
__device__ __forceinline__ void gemm128_tile(
    const float* __restrict__ A, const float* __restrict__ W,
    int row0, int col0, float c[8][8], float* As, float* Bs)
{
    int tid = threadIdx.x;
    int tx = tid & 15, ty = tid >> 4;

    for (int k0 = 0; k0 < CC; k0 += 8) {
        // Load A tile 128x8 (As[kk][m], padded stride 129)
        {
            int r  = tid >> 1;
            int cg = (tid & 1) * 4;
            float4 a4 = *(const float4*)(A + (size_t)(row0 + r) * CC + k0 + cg);
            As[(cg + 0) * 129 + r] = a4.x;
            As[(cg + 1) * 129 + r] = a4.y;
            As[(cg + 2) * 129 + r] = a4.z;
            As[(cg + 3) * 129 + r] = a4.w;
        }
        // Load W tile 8x128 (Bs[kk][n])
        {
            int r  = tid >> 5;
            int cg = (tid & 31) * 4;
            float4 b4 = *(const float4*)(W + (size_t)(k0 + r) * CC + col0 + cg);
            *(float4*)(Bs + r * 128 + cg) = b4;
        }
        __syncthreads();
        #pragma unroll
        for (int kk = 0; kk < 8; kk++) {
            float a[8], b[8];
            #pragma unroll
            for (int i = 0; i < 8; i++) a[i] = As[kk * 129 + ty * 8 + i];
            #pragma unroll
            for (int j = 0; j < 8; j++) b[j] = Bs[kk * 128 + tx * 8 + j];
            #pragma unroll
            for (int i = 0; i < 8; i++)
                #pragma unroll
                for (int j = 0; j < 8; j++)
                    c[i][j] += a[i] * b[j];
        }
        __syncthreads();
    }
}

// ---------------------------------------------------------------------------
// K1: q/k/v = x @ W + b   -> stored as (b, h, t, d)
// grid (4, 64, 3), block 256
// ---------------------------------------------------------------------------
__global__ __launch_bounds__(256) void qkv_gemm(
    const float* __restrict__ x,
    const float* __restrict__ Wq, const float* __restrict__ bq,
    const float* __restrict__ Wk, const float* __restrict__ bk,
    const float* __restrict__ Wv, const float* __restrict__ bv)
{
    __shared__ float As[8 * 129];
    __shared__ float Bs[8 * 128];
    int z = blockIdx.z;
    const float* W   = (z == 0) ? Wq : (z == 1) ? Wk : Wv;
    const float* bia = (z == 0) ? bq : (z == 1) ? bk : bv;
    float* out       = (z == 0) ? g_q : (z == 1) ? g_k : g_v;

    int row0 = blockIdx.y * 128, col0 = blockIdx.x * 128;
    float c[8][8];
    #pragma unroll
    for (int i = 0; i < 8; i++)
        #pragma unroll
        for (int j = 0; j < 8; j++) c[i][j] = 0.0f;

    gemm128_tile(x, W, row0, col0, c, As, Bs);

    int tx = threadIdx.x & 15, ty = threadIdx.x >> 4;
    int n0 = col0 + tx * 8;
    float bb[8];
    #pragma unroll
    for (int j = 0; j < 8; j++) bb[j] = bia[n0 + j];
    int h = n0 >> 6, d0 = n0 & 63;

    #pragma unroll
    for (int i = 0; i < 8; i++) {
        int m  = row0 + ty * 8 + i;
        int b_ = m >> 10, t = m & (TT - 1);
        size_t ob = (((size_t)b_ * HH + h) * TT + t) * HD + d0;
        float4 v0 = make_float4(c[i][0] + bb[0], c[i][1] + bb[1],
                                c[i][2] + bb[2], c[i][3] + bb[3]);
        float4 v1 = make_float4(c[i][4] + bb[4], c[i][5] + bb[5],
                                c[i][6] + bb[6], c[i][7] + bb[7]);
        *(float4*)(out + ob)     = v0;
        *(float4*)(out + ob + 4) = v1;
    }
}

// ---------------------------------------------------------------------------
// K2: proj[row, r] = q[row, :] . rel_k[r, :]   (row = bh*T + t), r in [0,137)
// grid (BH*TT/32), block 256
// ---------------------------------------------------------------------------
__global__ __launch_bounds__(256) void proj_kernel(const float* __restrict__ rel_k)
{
    __shared__ float qs[32 * 64];      // q rows tile
    __shared__ float rkt[64 * NR];     // rel_k transposed: rkt[d][r]
    int tid = threadIdx.x;
    int r0  = blockIdx.x * 32;

    for (int idx = tid; idx < 32 * 64; idx += 256)
        qs[idx] = g_q[(size_t)r0 * 64 + idx];
    for (int idx = tid; idx < 64 * NR; idx += 256) {
        int dd = idx / NR, r = idx - dd * NR;
        rkt[idx] = rel_k[r * 64 + dd];
    }
    __syncthreads();

    int tx = tid & 31, ty = tid >> 5;   // ty: 0..7 -> 4 t-rows each
    float c[4][5];
    #pragma unroll
    for (int i = 0; i < 4; i++)
        #pragma unroll
        for (int j = 0; j < 5; j++) c[i][j] = 0.0f;
    int rr[5];
    #pragma unroll
    for (int j = 0; j < 5; j++) { int r = tx + 32 * j; rr[j] = (r < NR) ? r : (NR - 1); }

    for (int dd = 0; dd < 64; dd++) {
        float qv[4], rv[5];
        #pragma unroll
        for (int i = 0; i < 4; i++) qv[i] = qs[(ty * 4 + i) * 64 + dd];
        #pragma unroll
        for (int j = 0; j < 5; j++) rv[j] = rkt[dd * NR + rr[j]];
        #pragma unroll
        for (int i = 0; i < 4; i++)
            #pragma unroll
            for (int j = 0; j < 5; j++) c[i][j] += qv[i] * rv[j];
    }

    #pragma unroll
    for (int i = 0; i < 4; i++) {
        size_t rowg = (size_t)(r0 + ty * 4 + i);
        #pragma unroll
        for (int j = 0; j < 5; j++) {
            int r = tx + 32 * j;
            if (r < NR) g_proj[rowg * NR + r] = c[i][j];
        }
    }
}

// ---------------------------------------------------------------------------
// K3: S[t,k] = (q[t].k[k] + proj[t, clip(k-t)+68]) * scale
// grid (8, 8, 64) = (k-tile, t-tile, bh), block 256, 8x8 microtile
// ---------------------------------------------------------------------------
__global__ __launch_bounds__(256) void s_kernel()
{
    __shared__ float Qs[16 * 129];
    __shared__ float Ks[16 * 129];
    int bh = blockIdx.z;
    int t0 = blockIdx.y * 128, k0 = blockIdx.x * 128;
    int tid = threadIdx.x;
    int tx = tid & 15, ty = tid >> 4;

    float c[8][8];
    #pragma unroll
    for (int i = 0; i < 8; i++)
        #pragma unroll
        for (int j = 0; j < 8; j++) c[i][j] = 0.0f;

    const float* qbase = g_q + (size_t)bh * TT * HD;
    const float* kbase = g_k + (size_t)bh * TT * HD;

    for (int dd0 = 0; dd0 < HD; dd0 += 16) {
        for (int n = tid; n < 512; n += 256) {
            int trow = n >> 2, c4 = (n & 3) * 4;
            float4 a4 = *(const float4*)(qbase + (size_t)(t0 + trow) * HD + dd0 + c4);
            Qs[(c4 + 0) * 129 + trow] = a4.x;
            Qs[(c4 + 1) * 129 + trow] = a4.y;
            Qs[(c4 + 2) * 129 + trow] = a4.z;
            Qs[(c4 + 3) * 129 + trow] = a4.w;
            float4 b4 = *(const float4*)(kbase + (size_t)(k0 + trow) * HD + dd0 + c4);
            Ks[(c4 + 0) * 129 + trow] = b4.x;
            Ks[(c4 + 1) * 129 + trow] = b4.y;
            Ks[(c4 + 2) * 129 + trow] = b4.z;
            Ks[(c4 + 3) * 129 + trow] = b4.w;
        }
        __syncthreads();
        #pragma unroll
        for (int dd = 0; dd < 16; dd++) {
            float a[8], b[8];
            #pragma unroll
            for (int i = 0; i < 8; i++) a[i] = Qs[dd * 129 + ty * 8 + i];
            #pragma unroll
            for (int j = 0; j < 8; j++) b[j] = Ks[dd * 129 + tx * 8 + j];
            #pragma unroll
            for (int i = 0; i < 8; i++)
                #pragma unroll
                for (int j = 0; j < 8; j++) c[i][j] += a[i] * b[j];
        }
        __syncthreads();
    }

    const float scale = 0.044194173824159216f;   // 1/sqrt(512)
    #pragma unroll
    for (int i = 0; i < 8; i++) {
        int tg = t0 + ty * 8 + i;
        const float* prow = g_proj + ((size_t)bh * TT + tg) * NR;
        float* srow = g_S + ((size_t)bh * TT + tg) * TT + k0 + tx * 8;
        float o[8];
        #pragma unroll
        for (int j = 0; j < 8; j++) {
            int kg = k0 + tx * 8 + j;
            int dist = kg - tg;
            dist = dist < -MAXR ? -MAXR : (dist > MAXR ? MAXR : dist);
            o[j] = (c[i][j] + prow[dist + MAXR]) * scale;
        }
        *(float4*)(srow)     = make_float4(o[0], o[1], o[2], o[3]);
        *(float4*)(srow + 4) = make_float4(o[4], o[5], o[6], o[7]);
    }
}

// ---------------------------------------------------------------------------
// K4: in-place row softmax of S + 137-bucket sums s[q, r]
// grid (1024, 64), block 256 (each thread owns 4 contiguous k's)
// ---------------------------------------------------------------------------
__global__ __launch_bounds__(256) void softmax_kernel()
{
    int t = blockIdx.x, bh = blockIdx.y;
    float* row = g_S + ((size_t)bh * TT + t) * TT;
    int tid = threadIdx.x;
    __shared__ float rbuf[256];
    __shared__ float s_sm[NR];

    for (int r = tid; r < NR; r += 256) s_sm[r] = 0.0f;

    float4 v = *(float4*)(row + tid * 4);
    float mx = fmaxf(fmaxf(v.x, v.y), fmaxf(v.z, v.w));
    rbuf[tid] = mx;
    __syncthreads();
    for (int s = 128; s > 0; s >>= 1) {
        if (tid < s) rbuf[tid] = fmaxf(rbuf[tid], rbuf[tid + s]);
        __syncthreads();
    }
    mx = rbuf[0];
    __syncthreads();

    float e[4];
    e[0] = __expf(v.x - mx); e[1] = __expf(v.y - mx);
    e[2] = __expf(v.z - mx); e[3] = __expf(v.w - mx);
    rbuf[tid] = e[0] + e[1] + e[2] + e[3];
    __syncthreads();
    for (int s = 128; s > 0; s >>= 1) {
        if (tid < s) rbuf[tid] += rbuf[tid + s];
        __syncthreads();
    }
    float inv = 1.0f / rbuf[0];
    __syncthreads();

    float p[4];
    #pragma unroll
    for (int m = 0; m < 4; m++) p[m] = e[m] * inv;
    *(float4*)(row + tid * 4) = make_float4(p[0], p[1], p[2], p[3]);

    float loc0 = 0.0f, loc1 = 0.0f;
    int kb = tid * 4;
    #pragma unroll
    for (int m = 0; m < 4; m++) {
        int d = kb + m - t;
        if (d <= -MAXR)      loc0 += p[m];
        else if (d >= MAXR)  loc1 += p[m];
        else                 s_sm[d + MAXR] = p[m];
    }
    rbuf[tid] = loc0;
    __syncthreads();
    for (int s = 128; s > 0; s >>= 1) {
        if (tid < s) rbuf[tid] += rbuf[tid + s];
        __syncthreads();
    }
    float tot0 = rbuf[0];
    __syncthreads();
    rbuf[tid] = loc1;
    __syncthreads();
    for (int s = 128; s > 0; s >>= 1) {
        if (tid < s) rbuf[tid] += rbuf[tid + s];
        __syncthreads();
    }
    float tot1 = rbuf[0];
    __syncthreads();
    if (tid == 0) { s_sm[0] = tot0; s_sm[NR - 1] = tot1; }
    __syncthreads();

    float* srow = g_sb + ((size_t)bh * TT + t) * NR;
    for (int r = tid; r < NR; r += 256) srow[r] = s_sm[r];
}

// ---------------------------------------------------------------------------
// K5: y[t, h*64+d] = sum_k P[t,k] V[k,d]  +  sum_r s[t,r] rel_v[r,d]
// grid (8, 64), block 256, 8x4 microtile, dynamic smem reused for epilogue
// ---------------------------------------------------------------------------
#define PV_SMEM_BYTES ((128 * 138 + NR * 64) * 4)   // 105728 B

__global__ __launch_bounds__(256) void pv_kernel(const float* __restrict__ rel_v)
{
    extern __shared__ float sm[];
    float* Ps = sm;                // 16*129
    float* Vs = sm + 16 * 129;     // 16*64
    int bh = blockIdx.y;
    int t0 = blockIdx.x * 128;
    int tid = threadIdx.x;
    int tx = tid & 15, ty = tid >> 4;

    float c[8][4];
    #pragma unroll
    for (int i = 0; i < 8; i++)
        #pragma unroll
        for (int j = 0; j < 4; j++) c[i][j] = 0.0f;

    const float* pbase = g_S + (size_t)bh * TT * TT;
    const float* vbase = g_v + (size_t)bh * TT * HD;

    for (int k0 = 0; k0 < TT; k0 += 16) {
        for (int n = tid; n < 512; n += 256) {
            int trow = n >> 2, c4 = (n & 3) * 4;
            float4 a4 = *(const float4*)(pbase + (size_t)(t0 + trow) * TT + k0 + c4);
            Ps[(c4 + 0) * 129 + trow] = a4.x;
            Ps[(c4 + 1) * 129 + trow] = a4.y;
            Ps[(c4 + 2) * 129 + trow] = a4.z;
            Ps[(c4 + 3) * 129 + trow] = a4.w;
        }
        {
            int krow = tid >> 4, c4 = (tid & 15) * 4;
            *(float4*)(Vs + krow * 64 + c4) =
                *(const float4*)(vbase + (size_t)(k0 + krow) * HD + c4);
        }
        __syncthreads();
        #pragma unroll
        for (int kk = 0; kk < 16; kk++) {
            float a[8], b[4];
            #pragma unroll
            for (int i = 0; i < 8; i++) a[i] = Ps[kk * 129 + ty * 8 + i];
            #pragma unroll
            for (int j = 0; j < 4; j++) b[j] = Vs[kk * 64 + tx * 4 + j];
            #pragma unroll
            for (int i = 0; i < 8; i++)
                #pragma unroll
                for (int j = 0; j < 4; j++) c[i][j] += a[i] * b[j];
        }
        __syncthreads();
    }

    // Epilogue: w2 = s @ rel_v, reusing smem
    float* s_sm = sm;                 // 128 * 138
    float* rvs  = sm + 128 * 138;     // 137 * 64
    const float* sbase = g_sb + ((size_t)bh * TT + t0) * NR;
    for (int idx = tid; idx < 128 * NR; idx += 256) {
        int i = idx / NR, r = idx - i * NR;
        s_sm[i * 138 + r] = sbase[(size_t)i * NR + r];
    }
    for (int idx = tid; idx < NR * 64; idx += 256) rvs[idx] = rel_v[idx];
    __syncthreads();

    for (int r = 0; r < NR; r++) {
        float rv[4];
        #pragma unroll
        for (int j = 0; j < 4; j++) rv[j] = rvs[r * 64 + tx * 4 + j];
        #pragma unroll
        for (int i = 0; i < 8; i++) {
            float sv = s_sm[(ty * 8 + i) * 138 + r];
            #pragma unroll
            for (int j = 0; j < 4; j++) c[i][j] += sv * rv[j];
        }
    }

    int b_ = bh >> 3, h = bh & 7;
    #pragma unroll
    for (int i = 0; i < 8; i++) {
        int t = t0 + ty * 8 + i;
        *(float4*)(g_y + ((size_t)(b_ * TT + t)) * CC + h * HD + tx * 4) =
            make_float4(c[i][0], c[i][1], c[i][2], c[i][3]);
    }
}

// ---------------------------------------------------------------------------
// K6: out = y @ Wo + bo
// grid (4, 64), block 256
// ---------------------------------------------------------------------------
__global__ __launch_bounds__(256) void out_gemm(
    const float* __restrict__ Wo, const float* __restrict__ bo,
    float* __restrict__ out)
{
    __shared__ float As[8 * 129];
    __shared__ float Bs[8 * 128];
    int row0 = blockIdx.y * 128, col0 = blockIdx.x * 128;
    float c[8][8];
    #pragma unroll
    for (int i = 0; i < 8; i++)
        #pragma unroll
        for (int j = 0; j < 8; j++) c[i][j] = 0.0f;

    gemm128_tile(g_y, Wo, row0, col0, c, As, Bs);

    int tx = threadIdx.x & 15, ty = threadIdx.x >> 4;
    int n0 = col0 + tx * 8;
    float bb[8];
    #pragma unroll
    for (int j = 0; j < 8; j++) bb[j] = bo[n0 + j];

    #pragma unroll
    for (int i = 0; i < 8; i++) {
        int m = row0 + ty * 8 + i;
        float4 v0 = make_float4(c[i][0] + bb[0], c[i][1] + bb[1],
                                c[i][2] + bb[2], c[i][3] + bb[3]);
        float4 v1 = make_float4(c[i][4] + bb[4], c[i][5] + bb[5],
                                c[i][6] + bb[6], c[i][7] + bb[7]);
        *(float4*)(out + (size_t)m * CC + n0)     = v0;
        *(float4*)(out + (size_t)m * CC + n0 + 4) = v1;
    }
}

// ---------------------------------------------------------------------------
extern "C" void kernel_launch(void* const* d_in, const int* in_sizes, int n_in,
                              void* d_out, int out_size)
{
    const float* x     = (const float*)d_in[0];
    const float* Wq    = (const float*)d_in[1];
    const float* bq    = (const float*)d_in[2];
    const float* Wk    = (const float*)d_in[3];
    const float* bk    = (const float*)d_in[4];
    const float* Wv    = (const float*)d_in[5];
    const float* bv    = (const float*)d_in[6];
    const float* Wo    = (const float*)d_in[7];
    const float* bo    = (const float*)d_in[8];
    const float* rel_k = (const float*)d_in[9];
    const float* rel_v = (const float*)d_in[10];
    float* out = (float*)d_out;

    cudaFuncSetAttribute(pv_kernel, cudaFuncAttributeMaxDynamicSharedMemorySize,
                         PV_SMEM_BYTES);

    qkv_gemm<<<dim3(4, 64, 3), 256>>>(x, Wq, bq, Wk, bk, Wv, bv);
    proj_kernel<<<BH * TT / 32, 256>>>(rel_k);
    s_kernel<<<dim3(8, 8, 64), 256>>>();
    softmax_kernel<<<dim3(1024, 64), 256>>>();
    pv_kernel<<<dim3(8, 64), 256, PV_SMEM_BYTES>>>(rel_v);
    out_gemm<<<dim3(4, 64), 256>>>(Wo, bo, out);
}

// round 2
// speedup vs baseline: 1.1077x; 1.1077x over previous
#include <cuda_runtime.h>

// Problem constants
#define BB   8
#define TT   1024
#define CC   512
#define HH   8
#define HD   64
#define NR   137      // 2*MAXR + 1
#define MAXR 68
#define BH   64       // BB*HH
#define MM   8192     // BB*TT

// Scratch (device globals; no runtime allocation allowed)
static __device__ float g_q[BH * TT * HD];          // (bh, t, d)
static __device__ float g_k[BH * TT * HD];
static __device__ float g_v[BH * TT * HD];
static __device__ float g_proj[BH * TT * NR];       // q . rel_k^T
static __device__ float g_S[67108864];              // (bh, t, k)  attn logits (268MB)
static __device__ float g_tm[BH * 8 * TT];          // per (bh, k-tile, t): tile max
static __device__ float g_ts[BH * 8 * TT];          // per (bh, k-tile, t): tile expsum
static __device__ float g_m[BH * TT];               // row max
static __device__ float g_l[BH * TT];               // row exp-sum (unnormalized)
static __device__ float g_y[MM * CC];               // pre-output-proj activations

// ---------------------------------------------------------------------------
// 128x128 fp32 GEMM tile helper: C[128,128] += A[row0:+128, :CC] * W[:, col0:+128]
// ---------------------------------------------------------------------------
__device__ __forceinline__ void gemm128_tile(
    const float* __restrict__ A, const float* __restrict__ W,
    int row0, int col0, float c[8][8], float* As, float* Bs)
{
    int tid = threadIdx.x;
    int tx = tid & 15, ty = tid >> 4;

    for (int k0 = 0; k0 < CC; k0 += 8) {
        {
            int r  = tid >> 1;
            int cg = (tid & 1) * 4;
            float4 a4 = *(const float4*)(A + (size_t)(row0 + r) * CC + k0 + cg);
            As[(cg + 0) * 129 + r] = a4.x;
            As[(cg + 1) * 129 + r] = a4.y;
            As[(cg + 2) * 129 + r] = a4.z;
            As[(cg + 3) * 129 + r] = a4.w;
        }
        {
            int r  = tid >> 5;
            int cg = (tid & 31) * 4;
            float4 b4 = *(const float4*)(W + (size_t)(k0 + r) * CC + col0 + cg);
            *(float4*)(Bs + r * 128 + cg) = b4;
        }
        __syncthreads();
        #pragma unroll
        for (int kk = 0; kk < 8; kk++) {
            float a[8], b[8];
            #pragma unroll
            for (int i = 0; i < 8; i++) a[i] = As[kk * 129 + ty * 8 + i];
            #pragma unroll
            for (int j = 0; j < 8; j++) b[j] = Bs[kk * 128 + tx * 8 + j];
            #pragma unroll
            for (int i = 0; i < 8; i++)
                #pragma unroll
                for (int j = 0; j < 8; j++)
                    c[i][j] += a[i] * b[j];
        }
        __syncthreads();
    }
}

// ---------------------------------------------------------------------------
// K1: q/k/v = x @ W + b   -> stored as (b, h, t, d)
// ---------------------------------------------------------------------------
__global__ __launch_bounds__(256) void qkv_gemm(
    const float* __restrict__ x,
    const float* __restrict__ Wq, const float* __restrict__ bq,
    const float* __restrict__ Wk, const float* __restrict__ bk,
    const float* __restrict__ Wv, const float* __restrict__ bv)
{
    __shared__ float As[8 * 129];
    __shared__ float Bs[8 * 128];
    int z = blockIdx.z;
    const float* W   = (z == 0) ? Wq : (z == 1) ? Wk : Wv;
    const float* bia = (z == 0) ? bq : (z == 1) ? bk : bv;
    float* out       = (z == 0) ? g_q : (z == 1) ? g_k : g_v;

    int row0 = blockIdx.y * 128, col0 = blockIdx.x * 128;
    float c[8][8];
    #pragma unroll
    for (int i = 0; i < 8; i++)
        #pragma unroll
        for (int j = 0; j < 8; j++) c[i][j] = 0.0f;

    gemm128_tile(x, W, row0, col0, c, As, Bs);

    int tx = threadIdx.x & 15, ty = threadIdx.x >> 4;
    int n0 = col0 + tx * 8;
    float bb[8];
    #pragma unroll
    for (int j = 0; j < 8; j++) bb[j] = bia[n0 + j];
    int h = n0 >> 6, d0 = n0 & 63;

    #pragma unroll
    for (int i = 0; i < 8; i++) {
        int m  = row0 + ty * 8 + i;
        int b_ = m >> 10, t = m & (TT - 1);
        size_t ob = (((size_t)b_ * HH + h) * TT + t) * HD + d0;
        float4 v0 = make_float4(c[i][0] + bb[0], c[i][1] + bb[1],
                                c[i][2] + bb[2], c[i][3] + bb[3]);
        float4 v1 = make_float4(c[i][4] + bb[4], c[i][5] + bb[5],
                                c[i][6] + bb[6], c[i][7] + bb[7]);
        *(float4*)(out + ob)     = v0;
        *(float4*)(out + ob + 4) = v1;
    }
}

// ---------------------------------------------------------------------------
// K2: proj[row, r] = q[row, :] . rel_k[r, :]
// ---------------------------------------------------------------------------
__global__ __launch_bounds__(256) void proj_kernel(const float* __restrict__ rel_k)
{
    __shared__ float qs[32 * 64];
    __shared__ float rkt[64 * NR];
    int tid = threadIdx.x;
    int r0  = blockIdx.x * 32;

    for (int idx = tid; idx < 32 * 64; idx += 256)
        qs[idx] = g_q[(size_t)r0 * 64 + idx];
    for (int idx = tid; idx < 64 * NR; idx += 256) {
        int dd = idx / NR, r = idx - dd * NR;
        rkt[idx] = rel_k[r * 64 + dd];
    }
    __syncthreads();

    int tx = tid & 31, ty = tid >> 5;
    float c[4][5];
    #pragma unroll
    for (int i = 0; i < 4; i++)
        #pragma unroll
        for (int j = 0; j < 5; j++) c[i][j] = 0.0f;
    int rr[5];
    #pragma unroll
    for (int j = 0; j < 5; j++) { int r = tx + 32 * j; rr[j] = (r < NR) ? r : (NR - 1); }

    for (int dd = 0; dd < 64; dd++) {
        float qv[4], rv[5];
        #pragma unroll
        for (int i = 0; i < 4; i++) qv[i] = qs[(ty * 4 + i) * 64 + dd];
        #pragma unroll
        for (int j = 0; j < 5; j++) rv[j] = rkt[dd * NR + rr[j]];
        #pragma unroll
        for (int i = 0; i < 4; i++)
            #pragma unroll
            for (int j = 0; j < 5; j++) c[i][j] += qv[i] * rv[j];
    }

    #pragma unroll
    for (int i = 0; i < 4; i++) {
        size_t rowg = (size_t)(r0 + ty * 4 + i);
        #pragma unroll
        for (int j = 0; j < 5; j++) {
            int r = tx + 32 * j;
            if (r < NR) g_proj[rowg * NR + r] = c[i][j];
        }
    }
}

// ---------------------------------------------------------------------------
// K3: S[t,k] = (q[t].k[k] + proj[t, clip(k-t)+68]) * scale
//     + per-row tile max & tile exp-sum via width-16 shuffles
// grid (8, 8, 64) = (k-tile, t-tile, bh), block 256
// ---------------------------------------------------------------------------
__global__ __launch_bounds__(256) void s_kernel()
{
    __shared__ float Qs[16 * 129];
    __shared__ float Ks[16 * 129];
    int bh = blockIdx.z;
    int t0 = blockIdx.y * 128, k0 = blockIdx.x * 128;
    int tid = threadIdx.x;
    int tx = tid & 15, ty = tid >> 4;

    float c[8][8];
    #pragma unroll
    for (int i = 0; i < 8; i++)
        #pragma unroll
        for (int j = 0; j < 8; j++) c[i][j] = 0.0f;

    const float* qbase = g_q + (size_t)bh * TT * HD;
    const float* kbase = g_k + (size_t)bh * TT * HD;

    for (int dd0 = 0; dd0 < HD; dd0 += 16) {
        for (int n = tid; n < 512; n += 256) {
            int trow = n >> 2, c4 = (n & 3) * 4;
            float4 a4 = *(const float4*)(qbase + (size_t)(t0 + trow) * HD + dd0 + c4);
            Qs[(c4 + 0) * 129 + trow] = a4.x;
            Qs[(c4 + 1) * 129 + trow] = a4.y;
            Qs[(c4 + 2) * 129 + trow] = a4.z;
            Qs[(c4 + 3) * 129 + trow] = a4.w;
            float4 b4 = *(const float4*)(kbase + (size_t)(k0 + trow) * HD + dd0 + c4);
            Ks[(c4 + 0) * 129 + trow] = b4.x;
            Ks[(c4 + 1) * 129 + trow] = b4.y;
            Ks[(c4 + 2) * 129 + trow] = b4.z;
            Ks[(c4 + 3) * 129 + trow] = b4.w;
        }
        __syncthreads();
        #pragma unroll
        for (int dd = 0; dd < 16; dd++) {
            float a[8], b[8];
            #pragma unroll
            for (int i = 0; i < 8; i++) a[i] = Qs[dd * 129 + ty * 8 + i];
            #pragma unroll
            for (int j = 0; j < 8; j++) b[j] = Ks[dd * 129 + tx * 8 + j];
            #pragma unroll
            for (int i = 0; i < 8; i++)
                #pragma unroll
                for (int j = 0; j < 8; j++) c[i][j] += a[i] * b[j];
        }
        __syncthreads();
    }

    const float scale = 0.044194173824159216f;   // 1/sqrt(512)
    #pragma unroll
    for (int i = 0; i < 8; i++) {
        int tg = t0 + ty * 8 + i;
        const float* prow = g_proj + ((size_t)bh * TT + tg) * NR;
        float* srow = g_S + ((size_t)bh * TT + tg) * TT + k0 + tx * 8;
        float o[8];
        #pragma unroll
        for (int j = 0; j < 8; j++) {
            int kg = k0 + tx * 8 + j;
            int dist = kg - tg;
            dist = dist < -MAXR ? -MAXR : (dist > MAXR ? MAXR : dist);
            o[j] = (c[i][j] + prow[dist + MAXR]) * scale;
        }
        *(float4*)(srow)     = make_float4(o[0], o[1], o[2], o[3]);
        *(float4*)(srow + 4) = make_float4(o[4], o[5], o[6], o[7]);

        // tile-row max across the 16 threads of this half-warp
        float mloc = o[0];
        #pragma unroll
        for (int j = 1; j < 8; j++) mloc = fmaxf(mloc, o[j]);
        #pragma unroll
        for (int off = 8; off >= 1; off >>= 1)
            mloc = fmaxf(mloc, __shfl_xor_sync(0xffffffffu, mloc, off, 16));
        float es = 0.0f;
        #pragma unroll
        for (int j = 0; j < 8; j++) es += __expf(o[j] - mloc);
        #pragma unroll
        for (int off = 8; off >= 1; off >>= 1)
            es += __shfl_xor_sync(0xffffffffu, es, off, 16);
        if (tx == 0) {
            size_t ob = ((size_t)bh * 8 + blockIdx.x) * TT + tg;
            g_tm[ob] = mloc;
            g_ts[ob] = es;
        }
    }
}

// ---------------------------------------------------------------------------
// K4: combine 8 per-tile (max, expsum) pairs into row (m, l)
// grid (64), block 1024
// ---------------------------------------------------------------------------
__global__ __launch_bounds__(1024) void reduce_ml()
{
    int bh = blockIdx.x;
    int t  = threadIdx.x;
    float tm[8], ts[8];
    #pragma unroll
    for (int i = 0; i < 8; i++) {
        size_t ob = ((size_t)bh * 8 + i) * TT + t;
        tm[i] = g_tm[ob];
        ts[i] = g_ts[ob];
    }
    float m = tm[0];
    #pragma unroll
    for (int i = 1; i < 8; i++) m = fmaxf(m, tm[i]);
    float l = 0.0f;
    #pragma unroll
    for (int i = 0; i < 8; i++) l += ts[i] * __expf(tm[i] - m);
    g_m[(size_t)bh * TT + t] = m;
    g_l[(size_t)bh * TT + t] = l;
}

// ---------------------------------------------------------------------------
// K5: fused exp + PV + band-bucket + rel_v epilogue
//   p = exp(S - m)  applied while loading S tiles
//   w1 = p @ V (unnormalized), band buckets captured in smem, P_lo accumulated,
//   P_hi = l - P_lo - sum(band); y = (w1 + w2) / l
// grid (8, 64), block 256
// ---------------------------------------------------------------------------
#define PV_PS    0                       // 16*129 = 2064
#define PV_VS    2064                    // 16*64  = 1024
#define PV_BAND  3088                    // 128*136 = 17408
#define PV_RELV  20496                   // 137*64 = 8768
#define PV_M     29264                   // 128
#define PV_L     29392                   // 128
#define PV_PLO   29520                   // 128
#define PV_FLOATS 29648
#define PV_SMEM_BYTES (PV_FLOATS * 4)    // 118592 B

__global__ __launch_bounds__(256) void pv_kernel(const float* __restrict__ rel_v)
{
    extern __shared__ float sm[];
    float* Ps    = sm + PV_PS;
    float* Vs    = sm + PV_VS;
    float* band  = sm + PV_BAND;
    float* rvs   = sm + PV_RELV;
    float* m_s   = sm + PV_M;
    float* l_s   = sm + PV_L;
    float* plo_s = sm + PV_PLO;

    int bh = blockIdx.y;
    int t0 = blockIdx.x * 128;
    int tid = threadIdx.x;
    int tx = tid & 15, ty = tid >> 4;

    // prologue: zero band, load m/l
    for (int idx = tid; idx < 128 * 136; idx += 256) band[idx] = 0.0f;
    if (tid < 128) {
        m_s[tid] = g_m[(size_t)bh * TT + t0 + tid];
        l_s[tid] = g_l[(size_t)bh * TT + t0 + tid];
    }
    __syncthreads();

    float c[8][4];
    #pragma unroll
    for (int i = 0; i < 8; i++)
        #pragma unroll
        for (int j = 0; j < 4; j++) c[i][j] = 0.0f;

    float plo_a = 0.0f, plo_b = 0.0f;   // rows tid>>2 and 64+(tid>>2)

    const float* pbase = g_S + (size_t)bh * TT * TT;
    const float* vbase = g_v + (size_t)bh * TT * HD;

    for (int k0 = 0; k0 < TT; k0 += 16) {
        #pragma unroll
        for (int half = 0; half < 2; half++) {
            int n = tid + half * 256;
            int trow = n >> 2, c4 = (n & 3) * 4;
            int tg = t0 + trow;
            float mrow = m_s[trow];
            float4 a4 = *(const float4*)(pbase + (size_t)tg * TT + k0 + c4);
            float pv0 = __expf(a4.x - mrow);
            float pv1 = __expf(a4.y - mrow);
            float pv2 = __expf(a4.z - mrow);
            float pv3 = __expf(a4.w - mrow);
            Ps[(c4 + 0) * 129 + trow] = pv0;
            Ps[(c4 + 1) * 129 + trow] = pv1;
            Ps[(c4 + 2) * 129 + trow] = pv2;
            Ps[(c4 + 3) * 129 + trow] = pv3;
            float pl = 0.0f;
            #pragma unroll
            for (int j = 0; j < 4; j++) {
                float pv = (j == 0) ? pv0 : (j == 1) ? pv1 : (j == 2) ? pv2 : pv3;
                int d = (k0 + c4 + j) - tg;
                if ((unsigned)(d + 67) <= 134u)
                    band[trow * 136 + d + 67] = pv;
                else if (d <= -MAXR)
                    pl += pv;
            }
            if (half == 0) plo_a += pl; else plo_b += pl;
        }
        {
            int krow = tid >> 4, c4v = (tid & 15) * 4;
            *(float4*)(Vs + krow * 64 + c4v) =
                *(const float4*)(vbase + (size_t)(k0 + krow) * HD + c4v);
        }
        __syncthreads();
        #pragma unroll
        for (int kk = 0; kk < 16; kk++) {
            float a[8], b[4];
            #pragma unroll
            for (int i = 0; i < 8; i++) a[i] = Ps[kk * 129 + ty * 8 + i];
            #pragma unroll
            for (int j = 0; j < 4; j++) b[j] = Vs[kk * 64 + tx * 4 + j];
            #pragma unroll
            for (int i = 0; i < 8; i++)
                #pragma unroll
                for (int j = 0; j < 4; j++) c[i][j] += a[i] * b[j];
        }
        __syncthreads();
    }

    // reduce plo over the 4 threads that share each row (lanes differ in bits 0-1)
    plo_a += __shfl_xor_sync(0xffffffffu, plo_a, 1);
    plo_a += __shfl_xor_sync(0xffffffffu, plo_a, 2);
    plo_b += __shfl_xor_sync(0xffffffffu, plo_b, 1);
    plo_b += __shfl_xor_sync(0xffffffffu, plo_b, 2);
    if ((tid & 3) == 0) {
        plo_s[tid >> 2]        = plo_a;
        plo_s[64 + (tid >> 2)] = plo_b;
    }
    // load rel_v into smem
    for (int idx = tid * 4; idx < NR * 64; idx += 256 * 4)
        *(float4*)(rvs + idx) = *(const float4*)(rel_v + idx);
    __syncthreads();

    // epilogue: w2 = buckets @ rel_v
    float intu[8];
    #pragma unroll
    for (int i = 0; i < 8; i++) intu[i] = 0.0f;

    for (int r = 1; r <= 135; r++) {
        float rv[4];
        #pragma unroll
        for (int j = 0; j < 4; j++) rv[j] = rvs[r * 64 + tx * 4 + j];
        #pragma unroll
        for (int i = 0; i < 8; i++) {
            float sv = band[(ty * 8 + i) * 136 + (r - 1)];
            intu[i] += sv;
            #pragma unroll
            for (int j = 0; j < 4; j++) c[i][j] += sv * rv[j];
        }
    }

    int b_ = bh >> 3, h = bh & 7;
    #pragma unroll
    for (int i = 0; i < 8; i++) {
        int row = ty * 8 + i;
        float plo = plo_s[row];
        float lr  = l_s[row];
        float phi = lr - plo - intu[i];
        float inv = 1.0f / lr;
        float o[4];
        #pragma unroll
        for (int j = 0; j < 4; j++) {
            float w = c[i][j] + plo * rvs[0 * 64 + tx * 4 + j]
                              + phi * rvs[136 * 64 + tx * 4 + j];
            o[j] = w * inv;
        }
        int t = t0 + row;
        *(float4*)(g_y + ((size_t)(b_ * TT + t)) * CC + h * HD + tx * 4) =
            make_float4(o[0], o[1], o[2], o[3]);
    }
}

// ---------------------------------------------------------------------------
// K6: out = y @ Wo + bo
// ---------------------------------------------------------------------------
__global__ __launch_bounds__(256) void out_gemm(
    const float* __restrict__ Wo, const float* __restrict__ bo,
    float* __restrict__ out)
{
    __shared__ float As[8 * 129];
    __shared__ float Bs[8 * 128];
    int row0 = blockIdx.y * 128, col0 = blockIdx.x * 128;
    float c[8][8];
    #pragma unroll
    for (int i = 0; i < 8; i++)
        #pragma unroll
        for (int j = 0; j < 8; j++) c[i][j] = 0.0f;

    gemm128_tile(g_y, Wo, row0, col0, c, As, Bs);

    int tx = threadIdx.x & 15, ty = threadIdx.x >> 4;
    int n0 = col0 + tx * 8;
    float bb[8];
    #pragma unroll
    for (int j = 0; j < 8; j++) bb[j] = bo[n0 + j];

    #pragma unroll
    for (int i = 0; i < 8; i++) {
        int m = row0 + ty * 8 + i;
        float4 v0 = make_float4(c[i][0] + bb[0], c[i][1] + bb[1],
                                c[i][2] + bb[2], c[i][3] + bb[3]);
        float4 v1 = make_float4(c[i][4] + bb[4], c[i][5] + bb[5],
                                c[i][6] + bb[6], c[i][7] + bb[7]);
        *(float4*)(out + (size_t)m * CC + n0)     = v0;
        *(float4*)(out + (size_t)m * CC + n0 + 4) = v1;
    }
}

// ---------------------------------------------------------------------------
extern "C" void kernel_launch(void* const* d_in, const int* in_sizes, int n_in,
                              void* d_out, int out_size)
{
    const float* x     = (const float*)d_in[0];
    const float* Wq    = (const float*)d_in[1];
    const float* bq    = (const float*)d_in[2];
    const float* Wk    = (const float*)d_in[3];
    const float* bk    = (const float*)d_in[4];
    const float* Wv    = (const float*)d_in[5];
    const float* bv    = (const float*)d_in[6];
    const float* Wo    = (const float*)d_in[7];
    const float* bo    = (const float*)d_in[8];
    const float* rel_k = (const float*)d_in[9];
    const float* rel_v = (const float*)d_in[10];
    float* out = (float*)d_out;

    cudaFuncSetAttribute(pv_kernel, cudaFuncAttributeMaxDynamicSharedMemorySize,
                         PV_SMEM_BYTES);

    qkv_gemm<<<dim3(4, 64, 3), 256>>>(x, Wq, bq, Wk, bk, Wv, bv);
    proj_kernel<<<BH * TT / 32, 256>>>(rel_k);
    s_kernel<<<dim3(8, 8, 64), 256>>>();
    reduce_ml<<<64, 1024>>>();
    pv_kernel<<<dim3(8, 64), 256, PV_SMEM_BYTES>>>(rel_v);
    out_gemm<<<dim3(4, 64), 256>>>(Wo, bo, out);
}